// round 5
// baseline (speedup 1.0000x reference)
#include <cuda_runtime.h>
#include <cuda_fp16.h>
#include <cstdint>

// ---------------------------------------------------------------------------
// out[i,n] = elu( sum_{c,y,x} conv[i,c,y,x] * Wc[n,c]*Wy[n,y]*Wx[n,x] + bias[n] )
// s[(i,c), n] = conv_flat[16384 x 1296] @ Wyx[8192 x 1296]^T   (fp16 HMMA GEMM)
// This round: f16-accumulate HMMA pairs (k=32) promoted to f32 — probes
// whether sm_103 legacy HMMA doubles at f16 accum (consumer-style pipe).
// tcgen05 unavailable: harness PTX target is sm_103 (no 'a' suffix).
// ---------------------------------------------------------------------------
#define MDIM 16384
#define NDIM 8192
#define KDIM 1296
#define KP   1344            // 21 * 64
#define NT   21
#define BM   128
#define BN   256
#define BK   64              // 64 halfs = 128B rows (SW128 atom)

#define A_TILE_BYTES (BM * BK * 2)                   // 16384
#define B_TILE_BYTES (BN * BK * 2)                   // 32768
#define STAGE_BYTES  (A_TILE_BYTES + B_TILE_BYTES)   // 49152
#define WC_PITCH 68
#define SMEM_WC    (3 * STAGE_BYTES)                 // 147456
#define SMEM_BIAS  (SMEM_WC + BN * WC_PITCH * 4)     // 217088
#define SMEM_TOTAL (SMEM_BIAS + BN * 4)              // 218112

// Pre-swizzled, tile-contiguous operand images (device globals: no-alloc rule)
__device__ __align__(1024) unsigned char g_A_t[(size_t)(MDIM / BM) * NT * A_TILE_BYTES]; // 44 MB
__device__ __align__(1024) unsigned char g_B_t[(size_t)(NDIM / BN) * NT * B_TILE_BYTES]; // 22 MB
__device__ int g_probe_sink;

// ---------------------------------------------------------------------------
__device__ __forceinline__ uint32_t smem_u32(const void* p) {
    uint32_t a;
    asm("{ .reg .u64 t; cvta.to.shared.u64 t, %1; cvt.u32.u64 %0, t; }" : "=r"(a) : "l"(p));
    return a;
}
__device__ __forceinline__ void cp16(uint32_t dst, const void* src) {
    asm volatile("cp.async.cg.shared.global [%0], [%1], 16;" :: "r"(dst), "l"(src));
}
#define CP_COMMIT() asm volatile("cp.async.commit_group;" ::: "memory")
#define CP_WAIT(n)  asm volatile("cp.async.wait_group %0;" :: "n"(n) : "memory")

#define LDSM4(R0, R1, R2, R3, ADDR)                                            \
    asm volatile("ldmatrix.sync.aligned.m8n8.x4.shared.b16 {%0,%1,%2,%3}, [%4];" \
                 : "=r"(R0), "=r"(R1), "=r"(R2), "=r"(R3) : "r"(ADDR))

// f16-accumulate MMA: D = A*B + 0   (C = zero)
#define MMA_F16_Z(D0, D1, A, B, Z)                                             \
    asm volatile("mma.sync.aligned.m16n8k16.row.col.f16.f16.f16.f16 "          \
                 "{%0,%1}, {%2,%3,%4,%5}, {%6,%7}, {%8,%8};"                   \
                 : "=r"(D0), "=r"(D1)                                          \
                 : "r"((A)[0]), "r"((A)[1]), "r"((A)[2]), "r"((A)[3]),         \
                   "r"((B)[0]), "r"((B)[1]), "r"(Z))

// f16-accumulate MMA: D += A*B
#define MMA_F16_ACC(D0, D1, A, B)                                              \
    asm volatile("mma.sync.aligned.m16n8k16.row.col.f16.f16.f16.f16 "          \
                 "{%0,%1}, {%2,%3,%4,%5}, {%6,%7}, {%0,%1};"                   \
                 : "+r"(D0), "+r"(D1)                                          \
                 : "r"((A)[0]), "r"((A)[1]), "r"((A)[2]), "r"((A)[3]),         \
                   "r"((B)[0]), "r"((B)[1]))

// ---------------------------------------------------------------------------
// Probe kernel: aligns ncu capture (absolute launch #4 -> gemm_fused_kernel)
// ---------------------------------------------------------------------------
__global__ void probe_kernel() { g_probe_sink = 1; }

// ---------------------------------------------------------------------------
// Prep A: conv fp32 -> fp16, tiled + SW128-swizzled image, K padded to 1344
// ---------------------------------------------------------------------------
__global__ void prepA_kernel(const float* __restrict__ conv) {
    int g = blockIdx.x * 256 + threadIdx.x;
    if (g >= MDIM * (KP / 8)) return;
    int m  = g / (KP / 8);
    int k0 = (g - m * (KP / 8)) * 8;

    __half2 h[4];
    if (k0 < KDIM) {   // 1296 = 162*8 -> granules fully in or out
        const float4* s = (const float4*)(conv + (size_t)m * KDIM + k0);
        float4 a = s[0], b = s[1];
        h[0] = __floats2half2_rn(a.x, a.y);
        h[1] = __floats2half2_rn(a.z, a.w);
        h[2] = __floats2half2_rn(b.x, b.y);
        h[3] = __floats2half2_rn(b.z, b.w);
    } else {
        h[0] = h[1] = h[2] = h[3] = __floats2half2_rn(0.f, 0.f);
    }
    int tm = m >> 7, row = m & 127, kt = k0 >> 6, kc = k0 & 63;
    uint32_t off = row * 128 + kc * 2;
    uint32_t sw  = off ^ ((off >> 3) & 0x70);
    *(uint4*)(g_A_t + (size_t)(tm * NT + kt) * A_TILE_BYTES + sw) = *(uint4*)h;
}

// ---------------------------------------------------------------------------
// Prep B: Wyx[n, y*36+x] = Wy[n,y]*Wx[n,x] -> fp16 tiled swizzled image
// ---------------------------------------------------------------------------
__global__ void prepB_kernel(const float* __restrict__ Wy, const float* __restrict__ Wx) {
    int g = blockIdx.x * 256 + threadIdx.x;
    if (g >= NDIM * (KP / 8)) return;
    int n  = g / (KP / 8);
    int k0 = (g - n * (KP / 8)) * 8;

    __half hv[8];
    if (k0 < KDIM) {
#pragma unroll
        for (int j = 0; j < 8; j++) {
            int k = k0 + j;
            int y = k / 36, x = k - y * 36;
            hv[j] = __float2half(Wy[n * 36 + y] * Wx[n * 36 + x]);
        }
    } else {
#pragma unroll
        for (int j = 0; j < 8; j++) hv[j] = __float2half(0.f);
    }
    int tn = n >> 8, row = n & 255, kt = k0 >> 6, kc = k0 & 63;
    uint32_t off = row * 128 + kc * 2;
    uint32_t sw  = off ^ ((off >> 3) & 0x70);
    *(uint4*)(g_B_t + (size_t)(tn * NT + kt) * B_TILE_BYTES + sw) = *(uint4*)hv;
}

// ---------------------------------------------------------------------------
// Fused GEMM: 128x256x64 tiles, 8 warps (64x64), ldmatrix + f16-acc HMMA pairs
// promoted to f32 every k=32, 3-stage cp.async, fused Wc reduce + bias + ELU.
// ---------------------------------------------------------------------------
__global__ void __launch_bounds__(256, 1) gemm_fused_kernel(
    const float* __restrict__ Wc, const float* __restrict__ bias,
    float* __restrict__ out)
{
    extern __shared__ unsigned char smem[];
    const uint32_t sbase = smem_u32(smem);
    const int tid = threadIdx.x, lane = tid & 31, wid = tid >> 5;
    const int wm = wid >> 2, wn = wid & 3;       // 2 x 4 warp grid
    const int m_tile = blockIdx.y, n_tile = blockIdx.x;

    // ---- prologue: Wc + bias ----
#pragma unroll
    for (int it = 0; it < 16; it++) {
        int idx = it * 256 + tid;
        int n = idx >> 4, ch = idx & 15;
        cp16(sbase + SMEM_WC + n * (WC_PITCH * 4) + ch * 16,
             Wc + (size_t)(n_tile * BN + n) * 64 + ch * 4);
    }
    if (tid < 64) cp16(sbase + SMEM_BIAS + tid * 16, bias + n_tile * BN + tid * 4);

#define ISSUE_STAGE(KT, BUF) do {                                              \
    const unsigned char* As_ = g_A_t + ((size_t)m_tile * NT + (KT)) * A_TILE_BYTES; \
    const unsigned char* Bs_ = g_B_t + ((size_t)n_tile * NT + (KT)) * B_TILE_BYTES; \
    uint32_t d_ = sbase + (BUF) * STAGE_BYTES;                                 \
    _Pragma("unroll")                                                          \
    for (int i_ = 0; i_ < 4; i_++)                                             \
        cp16(d_ + i_ * 4096 + tid * 16, As_ + i_ * 4096 + tid * 16);           \
    _Pragma("unroll")                                                          \
    for (int i_ = 0; i_ < 8; i_++)                                             \
        cp16(d_ + A_TILE_BYTES + i_ * 4096 + tid * 16, Bs_ + i_ * 4096 + tid * 16); \
} while (0)

    ISSUE_STAGE(0, 0); CP_COMMIT();
    ISSUE_STAGE(1, 1); CP_COMMIT();

    // ---- per-lane ldmatrix address constants (SW128) ----
    uint32_t a_rowoff[4], a_xor[4];
#pragma unroll
    for (int mt = 0; mt < 4; mt++) {
        int r = wm * 64 + mt * 16 + (lane & 15);
        a_rowoff[mt] = r * 128;
        a_xor[mt]    = (r & 7) << 4;
    }
    const int a_colhi = (lane >> 4) * 16;
    uint32_t b_rowoff[2], b_xor[2];
#pragma unroll
    for (int grp = 0; grp < 2; grp++) {
        int r = wn * 64 + grp * 32 + lane;
        b_rowoff[grp] = A_TILE_BYTES + r * 128;
        b_xor[grp]    = (r & 7) << 4;
    }

    float acc[4][8][4];
#pragma unroll
    for (int a = 0; a < 4; a++)
#pragma unroll
        for (int b = 0; b < 8; b++)
#pragma unroll
            for (int c = 0; c < 4; c++) acc[a][b][c] = 0.f;

    uint32_t afr[2][4][4];     // both halves of a ks-pair live together
    uint32_t bfr[2][8][2];

#define LOAD_FRAGS(KS, SB, BUF) do {                                           \
    const uint32_t colA_ = (KS) * 32 + a_colhi;                                \
    _Pragma("unroll")                                                          \
    for (int mt_ = 0; mt_ < 4; mt_++)                                          \
        LDSM4(afr[BUF][mt_][0], afr[BUF][mt_][1],                              \
              afr[BUF][mt_][2], afr[BUF][mt_][3],                              \
              (SB) + a_rowoff[mt_] + (colA_ ^ a_xor[mt_]));                    \
    _Pragma("unroll")                                                          \
    for (int grp_ = 0; grp_ < 2; grp_++) {                                     \
        _Pragma("unroll")                                                      \
        for (int kh_ = 0; kh_ < 2; kh_++) {                                    \
            uint32_t r0_, r1_, r2_, r3_;                                       \
            const uint32_t colB_ = (KS) * 32 + kh_ * 16;                       \
            LDSM4(r0_, r1_, r2_, r3_,                                          \
                  (SB) + b_rowoff[grp_] + (colB_ ^ b_xor[grp_]));              \
            bfr[BUF][grp_ * 4 + 0][kh_] = r0_;                                 \
            bfr[BUF][grp_ * 4 + 1][kh_] = r1_;                                 \
            bfr[BUF][grp_ * 4 + 2][kh_] = r2_;                                 \
            bfr[BUF][grp_ * 4 + 3][kh_] = r3_;                                 \
        }                                                                      \
    }                                                                          \
} while (0)

    const uint32_t zz = 0u;

    // ---- mainloop ----
#pragma unroll 1
    for (int kt = 0; kt < NT; kt++) {
        CP_WAIT(1);
        __syncthreads();
        if (kt + 2 < NT) ISSUE_STAGE(kt + 2, (kt + 2) % 3);
        CP_COMMIT();

        const uint32_t sb = sbase + (kt % 3) * STAGE_BYTES;
#pragma unroll
        for (int pair = 0; pair < 2; pair++) {
            LOAD_FRAGS(pair * 2,     sb, 0);
            LOAD_FRAGS(pair * 2 + 1, sb, 1);
#pragma unroll
            for (int mt = 0; mt < 4; mt++) {
#pragma unroll
                for (int nt = 0; nt < 8; nt++) {
                    uint32_t d0, d1;
                    MMA_F16_Z(d0, d1, afr[0][mt], bfr[0][nt], zz);
                    MMA_F16_ACC(d0, d1, afr[1][mt], bfr[1][nt]);
                    float2 lo = __half22float2(*(__half2*)&d0);
                    float2 hi = __half22float2(*(__half2*)&d1);
                    acc[mt][nt][0] += lo.x;
                    acc[mt][nt][1] += lo.y;
                    acc[mt][nt][2] += hi.x;
                    acc[mt][nt][3] += hi.y;
                }
            }
        }
    }
#undef ISSUE_STAGE
#undef LOAD_FRAGS

    // ---- fused epilogue ----
    const int q = lane >> 2, r = lane & 3;
    const float* sWc = (const float*)(smem + SMEM_WC);
    const float* sB  = (const float*)(smem + SMEM_BIAS);
    const int i_img  = m_tile * 2 + wm;
    float* orow = out + (size_t)i_img * NDIM + n_tile * BN;

#pragma unroll
    for (int nt = 0; nt < 8; nt++) {
        const int nA = wn * 64 + nt * 8 + r * 2;
        float s0 = 0.f, s1 = 0.f;
#pragma unroll
        for (int mt = 0; mt < 4; mt++) {
            const int clo = mt * 16 + q, chi = clo + 8;
            s0 += acc[mt][nt][0] * sWc[nA * WC_PITCH + clo]
                + acc[mt][nt][2] * sWc[nA * WC_PITCH + chi];
            s1 += acc[mt][nt][1] * sWc[(nA + 1) * WC_PITCH + clo]
                + acc[mt][nt][3] * sWc[(nA + 1) * WC_PITCH + chi];
        }
#pragma unroll
        for (int off = 4; off <= 16; off <<= 1) {
            s0 += __shfl_xor_sync(0xffffffffu, s0, off);
            s1 += __shfl_xor_sync(0xffffffffu, s1, off);
        }
        if (q == 0) {
            float t0 = s0 + sB[nA];
            float t1 = s1 + sB[nA + 1];
            float2 o;
            o.x = (t0 > 0.f) ? t0 : expm1f(t0);
            o.y = (t1 > 0.f) ? t1 : expm1f(t1);
            *(float2*)(orow + nA) = o;
        }
    }
}

// ---------------------------------------------------------------------------
extern "C" void kernel_launch(void* const* d_in, const int* in_sizes, int n_in,
                              void* d_out, int out_size) {
    const float* conv = (const float*)d_in[0];  // [256, 64, 36, 36]
    const float* Wc   = (const float*)d_in[1];  // [8192, 1, 64]
    const float* Wy   = (const float*)d_in[2];  // [8192, 1, 36]
    const float* Wx   = (const float*)d_in[3];  // [8192, 1, 36]
    const float* bias = (const float*)d_in[4];  // [8192]
    float* out = (float*)d_out;                 // [256, 8192]
    (void)in_sizes; (void)n_in; (void)out_size;

    cudaFuncSetAttribute(gemm_fused_kernel,
                         cudaFuncAttributeMaxDynamicSharedMemorySize, SMEM_TOTAL);

    probe_kernel<<<1, 1>>>();   // shifts ncu capture slot (#4) onto the GEMM
    prepA_kernel<<<(MDIM * (KP / 8) + 255) / 256, 256>>>(conv);
    prepB_kernel<<<(NDIM * (KP / 8) + 255) / 256, 256>>>(Wy, Wx);
    gemm_fused_kernel<<<dim3(NDIM / BN, MDIM / BM), 256, SMEM_TOTAL>>>(Wc, bias, out);
}

// round 6
// speedup vs baseline: 1.3236x; 1.3236x over previous
#include <cuda_runtime.h>
#include <cuda_fp16.h>
#include <cstdint>

// ---------------------------------------------------------------------------
// out[i,n] = elu( sum_{c,y,x} conv[i,c,y,x] * Wc[n,c]*Wy[n,y]*Wx[n,x] + bias[n] )
// s[(i,c), n] = conv_flat[16384 x 1296] @ Wyx[8192 x 1296]^T   (fp16 HMMA, f32 acc)
// R6: 512 threads / 16 warps (4 per SMSP) to saturate the legacy HMMA pipe
// (R5 profile: tensor pipe only ~60% busy at 8 warps / 2 per SMSP).
// tcgen05 unavailable: harness PTX target is sm_103 (no 'a' suffix).
// ---------------------------------------------------------------------------
#define MDIM 16384
#define NDIM 8192
#define KDIM 1296
#define KP   1344            // 21 * 64
#define NT   21
#define BM   128
#define BN   256
#define BK   64              // 64 halfs = 128B rows (SW128 atom)

#define A_TILE_BYTES (BM * BK * 2)                   // 16384
#define B_TILE_BYTES (BN * BK * 2)                   // 32768
#define STAGE_BYTES  (A_TILE_BYTES + B_TILE_BYTES)   // 49152
#define WC_PITCH 68
#define SMEM_WC    (3 * STAGE_BYTES)                 // 147456
#define SMEM_BIAS  (SMEM_WC + BN * WC_PITCH * 4)     // 217088
#define SMEM_TOTAL (SMEM_BIAS + BN * 4)              // 218112

// Pre-swizzled, tile-contiguous operand images (device globals: no-alloc rule)
__device__ __align__(1024) unsigned char g_A_t[(size_t)(MDIM / BM) * NT * A_TILE_BYTES]; // 44 MB
__device__ __align__(1024) unsigned char g_B_t[(size_t)(NDIM / BN) * NT * B_TILE_BYTES]; // 22 MB
__device__ int g_probe_sink;

// ---------------------------------------------------------------------------
__device__ __forceinline__ uint32_t smem_u32(const void* p) {
    uint32_t a;
    asm("{ .reg .u64 t; cvta.to.shared.u64 t, %1; cvt.u32.u64 %0, t; }" : "=r"(a) : "l"(p));
    return a;
}
__device__ __forceinline__ void cp16(uint32_t dst, const void* src) {
    asm volatile("cp.async.cg.shared.global [%0], [%1], 16;" :: "r"(dst), "l"(src));
}
#define CP_COMMIT() asm volatile("cp.async.commit_group;" ::: "memory")
#define CP_WAIT(n)  asm volatile("cp.async.wait_group %0;" :: "n"(n) : "memory")

#define LDSM4(R0, R1, R2, R3, ADDR)                                            \
    asm volatile("ldmatrix.sync.aligned.m8n8.x4.shared.b16 {%0,%1,%2,%3}, [%4];" \
                 : "=r"(R0), "=r"(R1), "=r"(R2), "=r"(R3) : "r"(ADDR))

#define MMA16816(D, A, B)                                                      \
    asm volatile("mma.sync.aligned.m16n8k16.row.col.f32.f16.f16.f32 "          \
                 "{%0,%1,%2,%3}, {%4,%5,%6,%7}, {%8,%9}, {%0,%1,%2,%3};"       \
                 : "+f"((D)[0]), "+f"((D)[1]), "+f"((D)[2]), "+f"((D)[3])      \
                 : "r"((A)[0]), "r"((A)[1]), "r"((A)[2]), "r"((A)[3]),         \
                   "r"((B)[0]), "r"((B)[1]))

// ---------------------------------------------------------------------------
// Probe kernel: keeps ncu capture slot (#4) on gemm_fused_kernel
// ---------------------------------------------------------------------------
__global__ void probe_kernel() { g_probe_sink = 1; }

// ---------------------------------------------------------------------------
// Prep A: conv fp32 -> fp16, tiled + SW128-swizzled image, K padded to 1344
// ---------------------------------------------------------------------------
__global__ void prepA_kernel(const float* __restrict__ conv) {
    int g = blockIdx.x * 256 + threadIdx.x;
    if (g >= MDIM * (KP / 8)) return;
    int m  = g / (KP / 8);
    int k0 = (g - m * (KP / 8)) * 8;

    __half2 h[4];
    if (k0 < KDIM) {   // 1296 = 162*8 -> granules fully in or out
        const float4* s = (const float4*)(conv + (size_t)m * KDIM + k0);
        float4 a = s[0], b = s[1];
        h[0] = __floats2half2_rn(a.x, a.y);
        h[1] = __floats2half2_rn(a.z, a.w);
        h[2] = __floats2half2_rn(b.x, b.y);
        h[3] = __floats2half2_rn(b.z, b.w);
    } else {
        h[0] = h[1] = h[2] = h[3] = __floats2half2_rn(0.f, 0.f);
    }
    int tm = m >> 7, row = m & 127, kt = k0 >> 6, kc = k0 & 63;
    uint32_t off = row * 128 + kc * 2;
    uint32_t sw  = off ^ ((off >> 3) & 0x70);
    *(uint4*)(g_A_t + (size_t)(tm * NT + kt) * A_TILE_BYTES + sw) = *(uint4*)h;
}

// ---------------------------------------------------------------------------
// Prep B: Wyx[n, y*36+x] = Wy[n,y]*Wx[n,x] -> fp16 tiled swizzled image
// ---------------------------------------------------------------------------
__global__ void prepB_kernel(const float* __restrict__ Wy, const float* __restrict__ Wx) {
    int g = blockIdx.x * 256 + threadIdx.x;
    if (g >= NDIM * (KP / 8)) return;
    int n  = g / (KP / 8);
    int k0 = (g - n * (KP / 8)) * 8;

    __half hv[8];
    if (k0 < KDIM) {
#pragma unroll
        for (int j = 0; j < 8; j++) {
            int k = k0 + j;
            int y = k / 36, x = k - y * 36;
            hv[j] = __float2half(Wy[n * 36 + y] * Wx[n * 36 + x]);
        }
    } else {
#pragma unroll
        for (int j = 0; j < 8; j++) hv[j] = __float2half(0.f);
    }
    int tn = n >> 8, row = n & 255, kt = k0 >> 6, kc = k0 & 63;
    uint32_t off = row * 128 + kc * 2;
    uint32_t sw  = off ^ ((off >> 3) & 0x70);
    *(uint4*)(g_B_t + (size_t)(tn * NT + kt) * B_TILE_BYTES + sw) = *(uint4*)hv;
}

// ---------------------------------------------------------------------------
// Fused GEMM: 128x256x64 tiles, 16 warps (warp tile 64x32, grid 2x8),
// ldmatrix + HMMA f32-acc, 3-stage cp.async, single sync per k-tile,
// fused Wc-reduce + bias + ELU epilogue.
// ---------------------------------------------------------------------------
__global__ void __launch_bounds__(512, 1) gemm_fused_kernel(
    const float* __restrict__ Wc, const float* __restrict__ bias,
    float* __restrict__ out)
{
    extern __shared__ unsigned char smem[];
    const uint32_t sbase = smem_u32(smem);
    const int tid = threadIdx.x, lane = tid & 31, wid = tid >> 5;
    const int wm = wid >> 3, wn = wid & 7;       // 2 x 8 warp grid, tile 64x32
    const int m_tile = blockIdx.y, n_tile = blockIdx.x;

    // ---- prologue: Wc + bias ----
#pragma unroll
    for (int it = 0; it < 8; it++) {
        int idx = it * 512 + tid;
        int n = idx >> 4, ch = idx & 15;
        cp16(sbase + SMEM_WC + n * (WC_PITCH * 4) + ch * 16,
             Wc + (size_t)(n_tile * BN + n) * 64 + ch * 4);
    }
    if (tid < 64) cp16(sbase + SMEM_BIAS + tid * 16, bias + n_tile * BN + tid * 4);

#define ISSUE_STAGE(KT, BUF) do {                                              \
    const unsigned char* As_ = g_A_t + ((size_t)m_tile * NT + (KT)) * A_TILE_BYTES; \
    const unsigned char* Bs_ = g_B_t + ((size_t)n_tile * NT + (KT)) * B_TILE_BYTES; \
    uint32_t d_ = sbase + (BUF) * STAGE_BYTES;                                 \
    _Pragma("unroll")                                                          \
    for (int i_ = 0; i_ < 2; i_++)                                             \
        cp16(d_ + i_ * 8192 + tid * 16, As_ + i_ * 8192 + tid * 16);           \
    _Pragma("unroll")                                                          \
    for (int i_ = 0; i_ < 4; i_++)                                             \
        cp16(d_ + A_TILE_BYTES + i_ * 8192 + tid * 16, Bs_ + i_ * 8192 + tid * 16); \
} while (0)

    ISSUE_STAGE(0, 0); CP_COMMIT();
    ISSUE_STAGE(1, 1); CP_COMMIT();

    // ---- per-lane ldmatrix address constants (SW128) ----
    uint32_t a_rowoff[4], a_xor[4];
#pragma unroll
    for (int mt = 0; mt < 4; mt++) {
        int r = wm * 64 + mt * 16 + (lane & 15);
        a_rowoff[mt] = r * 128;
        a_xor[mt]    = (r & 7) << 4;
    }
    const int a_colhi = (lane >> 4) * 16;
    const int brow = wn * 32 + lane;             // 32 B-rows per warp
    const uint32_t b_rowoff = A_TILE_BYTES + brow * 128;
    const uint32_t b_xor    = (brow & 7) << 4;

    float acc[4][4][4];
#pragma unroll
    for (int a = 0; a < 4; a++)
#pragma unroll
        for (int b = 0; b < 4; b++)
#pragma unroll
            for (int c = 0; c < 4; c++) acc[a][b][c] = 0.f;

    // ---- mainloop: one sync per k-tile ----
#pragma unroll 1
    for (int kt = 0; kt < NT; kt++) {
        CP_WAIT(1);
        __syncthreads();
        if (kt + 2 < NT) ISSUE_STAGE(kt + 2, (kt + 2) % 3);
        CP_COMMIT();   // unconditional: uniform group counting

        const uint32_t sb = sbase + (kt % 3) * STAGE_BYTES;
#pragma unroll
        for (int ks = 0; ks < 4; ks++) {
            uint32_t afr[4][4];
            const uint32_t colA = ks * 32 + a_colhi;
#pragma unroll
            for (int mt = 0; mt < 4; mt++)
                LDSM4(afr[mt][0], afr[mt][1], afr[mt][2], afr[mt][3],
                      sb + a_rowoff[mt] + (colA ^ a_xor[mt]));

            uint32_t bfr[4][2];
#pragma unroll
            for (int kh = 0; kh < 2; kh++) {
                uint32_t r0, r1, r2, r3;
                const uint32_t colB = ks * 32 + kh * 16;
                LDSM4(r0, r1, r2, r3, sb + b_rowoff + (colB ^ b_xor));
                bfr[0][kh] = r0; bfr[1][kh] = r1;
                bfr[2][kh] = r2; bfr[3][kh] = r3;
            }
#pragma unroll
            for (int mt = 0; mt < 4; mt++)
#pragma unroll
                for (int nt = 0; nt < 4; nt++)
                    MMA16816(acc[mt][nt], afr[mt], bfr[nt]);
        }
    }
#undef ISSUE_STAGE

    // ---- fused epilogue ----
    // warp wm owns image i = m_tile*2 + wm (its 64 rows are that image's 64 c)
    const int q = lane >> 2, r = lane & 3;
    const float* sWc = (const float*)(smem + SMEM_WC);
    const float* sB  = (const float*)(smem + SMEM_BIAS);
    const int i_img  = m_tile * 2 + wm;
    float* orow = out + (size_t)i_img * NDIM + n_tile * BN;

#pragma unroll
    for (int nt = 0; nt < 4; nt++) {
        const int nA = wn * 32 + nt * 8 + r * 2;
        float s0 = 0.f, s1 = 0.f;
#pragma unroll
        for (int mt = 0; mt < 4; mt++) {
            const int clo = mt * 16 + q, chi = clo + 8;
            s0 += acc[mt][nt][0] * sWc[nA * WC_PITCH + clo]
                + acc[mt][nt][2] * sWc[nA * WC_PITCH + chi];
            s1 += acc[mt][nt][1] * sWc[(nA + 1) * WC_PITCH + clo]
                + acc[mt][nt][3] * sWc[(nA + 1) * WC_PITCH + chi];
        }
#pragma unroll
        for (int off = 4; off <= 16; off <<= 1) {
            s0 += __shfl_xor_sync(0xffffffffu, s0, off);
            s1 += __shfl_xor_sync(0xffffffffu, s1, off);
        }
        if (q == 0) {
            float t0 = s0 + sB[nA];
            float t1 = s1 + sB[nA + 1];
            float2 o;
            o.x = (t0 > 0.f) ? t0 : expm1f(t0);
            o.y = (t1 > 0.f) ? t1 : expm1f(t1);
            *(float2*)(orow + nA) = o;
        }
    }
}

// ---------------------------------------------------------------------------
extern "C" void kernel_launch(void* const* d_in, const int* in_sizes, int n_in,
                              void* d_out, int out_size) {
    const float* conv = (const float*)d_in[0];  // [256, 64, 36, 36]
    const float* Wc   = (const float*)d_in[1];  // [8192, 1, 64]
    const float* Wy   = (const float*)d_in[2];  // [8192, 1, 36]
    const float* Wx   = (const float*)d_in[3];  // [8192, 1, 36]
    const float* bias = (const float*)d_in[4];  // [8192]
    float* out = (float*)d_out;                 // [256, 8192]
    (void)in_sizes; (void)n_in; (void)out_size;

    cudaFuncSetAttribute(gemm_fused_kernel,
                         cudaFuncAttributeMaxDynamicSharedMemorySize, SMEM_TOTAL);

    probe_kernel<<<1, 1>>>();   // keeps ncu capture slot on the GEMM
    prepA_kernel<<<(MDIM * (KP / 8) + 255) / 256, 256>>>(conv);
    prepB_kernel<<<(NDIM * (KP / 8) + 255) / 256, 256>>>(Wy, Wx);
    gemm_fused_kernel<<<dim3(NDIM / BN, MDIM / BM), 512, SMEM_TOTAL>>>(Wc, bias, out);
}

// round 7
// speedup vs baseline: 1.4074x; 1.0633x over previous
#include <cuda_runtime.h>
#include <cuda_fp16.h>
#include <cstdint>

// ---------------------------------------------------------------------------
// out[i,n] = elu( sum_{c,y,x} conv[i,c,y,x] * Wc[n,c]*Wy[n,y]*Wx[n,x] + bias[n] )
// s[(i,c), n] = conv_flat[16384 x 1296] @ Wyx[8192 x 1296]^T   (fp16 HMMA, f32 acc)
// R7: 2 CTAs/SM (BN=128, 2-stage, 101KB smem, <=128 regs) so independent CTAs
// cover each other's barrier/LDSM phases (tensor pipe pinned ~60% with 1 CTA).
// tcgen05 unavailable: harness PTX target is sm_103 (no 'a' suffix).
// ---------------------------------------------------------------------------
#define MDIM 16384
#define NDIM 8192
#define KDIM 1296
#define KP   1344            // 21 * 64
#define NT   21
#define BM   128
#define BN   128
#define BK   64              // 64 halfs = 128B rows (SW128 atom)

#define A_TILE_BYTES (BM * BK * 2)                   // 16384
#define B_TILE_BYTES (BN * BK * 2)                   // 16384
#define STAGE_BYTES  (A_TILE_BYTES + B_TILE_BYTES)   // 32768
#define WC_PITCH 68
#define SMEM_WC    (2 * STAGE_BYTES)                 // 65536
#define SMEM_BIAS  (SMEM_WC + BN * WC_PITCH * 4)     // 100352
#define SMEM_TOTAL (SMEM_BIAS + BN * 4)              // 100864  (2 CTAs < 227KB)

// Pre-swizzled, tile-contiguous operand images (device globals: no-alloc rule)
__device__ __align__(1024) unsigned char g_A_t[(size_t)(MDIM / BM) * NT * A_TILE_BYTES]; // 44 MB
__device__ __align__(1024) unsigned char g_B_t[(size_t)(NDIM / BN) * NT * B_TILE_BYTES]; // 44 MB
__device__ int g_probe_sink;

// ---------------------------------------------------------------------------
__device__ __forceinline__ uint32_t smem_u32(const void* p) {
    uint32_t a;
    asm("{ .reg .u64 t; cvta.to.shared.u64 t, %1; cvt.u32.u64 %0, t; }" : "=r"(a) : "l"(p));
    return a;
}
__device__ __forceinline__ void cp16(uint32_t dst, const void* src) {
    asm volatile("cp.async.cg.shared.global [%0], [%1], 16;" :: "r"(dst), "l"(src));
}
#define CP_COMMIT() asm volatile("cp.async.commit_group;" ::: "memory")
#define CP_WAIT(n)  asm volatile("cp.async.wait_group %0;" :: "n"(n) : "memory")

#define LDSM4(R0, R1, R2, R3, ADDR)                                            \
    asm volatile("ldmatrix.sync.aligned.m8n8.x4.shared.b16 {%0,%1,%2,%3}, [%4];" \
                 : "=r"(R0), "=r"(R1), "=r"(R2), "=r"(R3) : "r"(ADDR))

#define MMA16816(D, A, B)                                                      \
    asm volatile("mma.sync.aligned.m16n8k16.row.col.f32.f16.f16.f32 "          \
                 "{%0,%1,%2,%3}, {%4,%5,%6,%7}, {%8,%9}, {%0,%1,%2,%3};"       \
                 : "+f"((D)[0]), "+f"((D)[1]), "+f"((D)[2]), "+f"((D)[3])      \
                 : "r"((A)[0]), "r"((A)[1]), "r"((A)[2]), "r"((A)[3]),         \
                   "r"((B)[0]), "r"((B)[1]))

// ---------------------------------------------------------------------------
__global__ void probe_kernel() { g_probe_sink = 1; }   // ncu slot #4 -> GEMM

// ---------------------------------------------------------------------------
// Prep A: conv fp32 -> fp16, tiled + SW128-swizzled image, K padded to 1344
// ---------------------------------------------------------------------------
__global__ void prepA_kernel(const float* __restrict__ conv) {
    int g = blockIdx.x * 256 + threadIdx.x;
    if (g >= MDIM * (KP / 8)) return;
    int m  = g / (KP / 8);
    int k0 = (g - m * (KP / 8)) * 8;

    __half2 h[4];
    if (k0 < KDIM) {   // 1296 = 162*8 -> granules fully in or out
        const float4* s = (const float4*)(conv + (size_t)m * KDIM + k0);
        float4 a = s[0], b = s[1];
        h[0] = __floats2half2_rn(a.x, a.y);
        h[1] = __floats2half2_rn(a.z, a.w);
        h[2] = __floats2half2_rn(b.x, b.y);
        h[3] = __floats2half2_rn(b.z, b.w);
    } else {
        h[0] = h[1] = h[2] = h[3] = __floats2half2_rn(0.f, 0.f);
    }
    int tm = m >> 7, row = m & 127, kt = k0 >> 6, kc = k0 & 63;
    uint32_t off = row * 128 + kc * 2;
    uint32_t sw  = off ^ ((off >> 3) & 0x70);
    *(uint4*)(g_A_t + (size_t)(tm * NT + kt) * A_TILE_BYTES + sw) = *(uint4*)h;
}

// ---------------------------------------------------------------------------
// Prep B: Wyx[n, y*36+x] = Wy[n,y]*Wx[n,x] -> fp16 tiled swizzled image (BN=128)
// ---------------------------------------------------------------------------
__global__ void prepB_kernel(const float* __restrict__ Wy, const float* __restrict__ Wx) {
    int g = blockIdx.x * 256 + threadIdx.x;
    if (g >= NDIM * (KP / 8)) return;
    int n  = g / (KP / 8);
    int k0 = (g - n * (KP / 8)) * 8;

    __half hv[8];
    if (k0 < KDIM) {
#pragma unroll
        for (int j = 0; j < 8; j++) {
            int k = k0 + j;
            int y = k / 36, x = k - y * 36;
            hv[j] = __float2half(Wy[n * 36 + y] * Wx[n * 36 + x]);
        }
    } else {
#pragma unroll
        for (int j = 0; j < 8; j++) hv[j] = __float2half(0.f);
    }
    int tn = n >> 7, row = n & 127, kt = k0 >> 6, kc = k0 & 63;
    uint32_t off = row * 128 + kc * 2;
    uint32_t sw  = off ^ ((off >> 3) & 0x70);
    *(uint4*)(g_B_t + (size_t)(tn * NT + kt) * B_TILE_BYTES + sw) = *(uint4*)hv;
}

// ---------------------------------------------------------------------------
// Fused GEMM: 128x128x64 tiles, 8 warps (warp tile 64x32, 2x4 grid),
// 2-stage cp.async, 2 CTAs/SM, fused Wc-reduce + bias + ELU epilogue.
// ---------------------------------------------------------------------------
__global__ void __launch_bounds__(256, 2) gemm_fused_kernel(
    const float* __restrict__ Wc, const float* __restrict__ bias,
    float* __restrict__ out)
{
    extern __shared__ unsigned char smem[];
    const uint32_t sbase = smem_u32(smem);
    const int tid = threadIdx.x, lane = tid & 31, wid = tid >> 5;
    const int wm = wid >> 2, wn = wid & 3;       // 2 x 4 warp grid, tile 64x32
    const int m_tile = blockIdx.y, n_tile = blockIdx.x;

    // ---- prologue: Wc + bias ----
#pragma unroll
    for (int it = 0; it < 8; it++) {
        int idx = it * 256 + tid;
        int n = idx >> 4, ch = idx & 15;
        cp16(sbase + SMEM_WC + n * (WC_PITCH * 4) + ch * 16,
             Wc + (size_t)(n_tile * BN + n) * 64 + ch * 4);
    }
    if (tid < 32) cp16(sbase + SMEM_BIAS + tid * 16, bias + n_tile * BN + tid * 4);

#define ISSUE_STAGE(KT, BUF) do {                                              \
    const unsigned char* As_ = g_A_t + ((size_t)m_tile * NT + (KT)) * A_TILE_BYTES; \
    const unsigned char* Bs_ = g_B_t + ((size_t)n_tile * NT + (KT)) * B_TILE_BYTES; \
    uint32_t d_ = sbase + (BUF) * STAGE_BYTES;                                 \
    _Pragma("unroll")                                                          \
    for (int i_ = 0; i_ < 4; i_++)                                             \
        cp16(d_ + i_ * 4096 + tid * 16, As_ + i_ * 4096 + tid * 16);           \
    _Pragma("unroll")                                                          \
    for (int i_ = 0; i_ < 4; i_++)                                             \
        cp16(d_ + A_TILE_BYTES + i_ * 4096 + tid * 16, Bs_ + i_ * 4096 + tid * 16); \
} while (0)

    ISSUE_STAGE(0, 0); CP_COMMIT();
    ISSUE_STAGE(1, 1); CP_COMMIT();

    // ---- per-lane ldmatrix address constants (SW128) ----
    uint32_t a_rowoff[4], a_xor[4];
#pragma unroll
    for (int mt = 0; mt < 4; mt++) {
        int r = wm * 64 + mt * 16 + (lane & 15);
        a_rowoff[mt] = r * 128;
        a_xor[mt]    = (r & 7) << 4;
    }
    const int a_colhi = (lane >> 4) * 16;
    const int brow = wn * 32 + lane;             // 32 B-rows per warp
    const uint32_t b_rowoff = A_TILE_BYTES + brow * 128;
    const uint32_t b_xor    = (brow & 7) << 4;

    float acc[4][4][4];
#pragma unroll
    for (int a = 0; a < 4; a++)
#pragma unroll
        for (int b = 0; b < 4; b++)
#pragma unroll
            for (int c = 0; c < 4; c++) acc[a][b][c] = 0.f;

    // ---- mainloop (2-stage: compute buf kt&1, then refill it with kt+2) ----
#pragma unroll 1
    for (int kt = 0; kt < NT; kt++) {
        CP_WAIT(1);
        __syncthreads();

        const uint32_t sb = sbase + (kt & 1) * STAGE_BYTES;
#pragma unroll
        for (int ks = 0; ks < 4; ks++) {
            uint32_t afr[4][4];
            const uint32_t colA = ks * 32 + a_colhi;
#pragma unroll
            for (int mt = 0; mt < 4; mt++)
                LDSM4(afr[mt][0], afr[mt][1], afr[mt][2], afr[mt][3],
                      sb + a_rowoff[mt] + (colA ^ a_xor[mt]));

            uint32_t bfr[4][2];
#pragma unroll
            for (int kh = 0; kh < 2; kh++) {
                uint32_t r0, r1, r2, r3;
                const uint32_t colB = ks * 32 + kh * 16;
                LDSM4(r0, r1, r2, r3, sb + b_rowoff + (colB ^ b_xor));
                bfr[0][kh] = r0; bfr[1][kh] = r1;
                bfr[2][kh] = r2; bfr[3][kh] = r3;
            }
#pragma unroll
            for (int mt = 0; mt < 4; mt++)
#pragma unroll
                for (int nt = 0; nt < 4; nt++)
                    MMA16816(acc[mt][nt], afr[mt], bfr[nt]);
        }
        __syncthreads();
        if (kt + 2 < NT) ISSUE_STAGE(kt + 2, kt & 1);
        CP_COMMIT();   // unconditional: uniform group counting
    }
#undef ISSUE_STAGE

    // ---- fused epilogue ----
    // warp wm owns image i = m_tile*2 + wm (its 64 rows = that image's 64 c)
    const int q = lane >> 2, r = lane & 3;
    const float* sWc = (const float*)(smem + SMEM_WC);
    const float* sB  = (const float*)(smem + SMEM_BIAS);
    const int i_img  = m_tile * 2 + wm;
    float* orow = out + (size_t)i_img * NDIM + n_tile * BN;

#pragma unroll
    for (int nt = 0; nt < 4; nt++) {
        const int nA = wn * 32 + nt * 8 + r * 2;
        float s0 = 0.f, s1 = 0.f;
#pragma unroll
        for (int mt = 0; mt < 4; mt++) {
            const int clo = mt * 16 + q, chi = clo + 8;
            s0 += acc[mt][nt][0] * sWc[nA * WC_PITCH + clo]
                + acc[mt][nt][2] * sWc[nA * WC_PITCH + chi];
            s1 += acc[mt][nt][1] * sWc[(nA + 1) * WC_PITCH + clo]
                + acc[mt][nt][3] * sWc[(nA + 1) * WC_PITCH + chi];
        }
#pragma unroll
        for (int off = 4; off <= 16; off <<= 1) {
            s0 += __shfl_xor_sync(0xffffffffu, s0, off);
            s1 += __shfl_xor_sync(0xffffffffu, s1, off);
        }
        if (q == 0) {
            float t0 = s0 + sB[nA];
            float t1 = s1 + sB[nA + 1];
            float2 o;
            o.x = (t0 > 0.f) ? t0 : expm1f(t0);
            o.y = (t1 > 0.f) ? t1 : expm1f(t1);
            *(float2*)(orow + nA) = o;
        }
    }
}

// ---------------------------------------------------------------------------
extern "C" void kernel_launch(void* const* d_in, const int* in_sizes, int n_in,
                              void* d_out, int out_size) {
    const float* conv = (const float*)d_in[0];  // [256, 64, 36, 36]
    const float* Wc   = (const float*)d_in[1];  // [8192, 1, 64]
    const float* Wy   = (const float*)d_in[2];  // [8192, 1, 36]
    const float* Wx   = (const float*)d_in[3];  // [8192, 1, 36]
    const float* bias = (const float*)d_in[4];  // [8192]
    float* out = (float*)d_out;                 // [256, 8192]
    (void)in_sizes; (void)n_in; (void)out_size;

    cudaFuncSetAttribute(gemm_fused_kernel,
                         cudaFuncAttributeMaxDynamicSharedMemorySize, SMEM_TOTAL);

    probe_kernel<<<1, 1>>>();   // keeps ncu capture slot on the GEMM
    prepA_kernel<<<(MDIM * (KP / 8) + 255) / 256, 256>>>(conv);
    prepB_kernel<<<(NDIM * (KP / 8) + 255) / 256, 256>>>(Wy, Wx);
    gemm_fused_kernel<<<dim3(NDIM / BN, MDIM / BM), 256, SMEM_TOTAL>>>(Wc, bias, out);
}